// round 1
// baseline (speedup 1.0000x reference)
#include <cuda_runtime.h>
#include <math_constants.h>
#include <cstdint>

#define Bb   2
#define Nq   2048
#define Mk   4096
#define Dd   256
#define Hh   8
#define DK   32
#define KNNk 16

// ---------------- scratch (static device globals; no allocation) ----------------
__device__ float g_Q[(size_t)Bb * Nq * Dd];    // 4 MB
__device__ float g_K[(size_t)Bb * Mk * Dd];    // 8 MB
__device__ float g_V[(size_t)Bb * Mk * Dd];    // 8 MB
__device__ float g_X[(size_t)Bb * Nq * Dd];    // attn out + residual
__device__ float g_T[(size_t)Bb * Nq * Dd];    // pre-LN
__device__ float g_Hb[(size_t)Bb * Nq * Dd];   // post LN+relu
__device__ int   g_idx[(size_t)Bb * Nq * KNNk];

// ---------------- GEMM: C[rows,256] = A[rows,256] @ W[256,256] + bias ----------------
// 64x64 tile, 256 threads, 4x4 per-thread microtile, K-chunks of 16.
__global__ void gemm_bias_kernel(const float* __restrict__ A,
                                 const float* __restrict__ W,
                                 const float* __restrict__ bias,
                                 float* __restrict__ C)
{
    __shared__ float As[16][68];   // [k][row], padded
    __shared__ float Ws[16][68];   // [k][col], padded (68*4B = 272B row stride, 16B aligned)

    const int tid  = threadIdx.x;
    const int row0 = blockIdx.y * 64;
    const int col0 = blockIdx.x * 64;
    const int tx = tid & 15;       // col group (4 cols)
    const int ty = tid >> 4;       // row group (4 rows)

    const int lr = tid >> 2;            // A-load: row 0..63
    const int lk = (tid & 3) * 4;       // A-load: k offset 0..12
    const int wk = tid >> 4;            // W-load: k 0..15
    const int wc = (tid & 15) * 4;      // W-load: col offset

    float acc[4][4];
#pragma unroll
    for (int r = 0; r < 4; r++)
#pragma unroll
        for (int c = 0; c < 4; c++) acc[r][c] = 0.f;

    for (int k0 = 0; k0 < 256; k0 += 16) {
        float4 a = *(const float4*)&A[(size_t)(row0 + lr) * 256 + k0 + lk];
        float4 w = *(const float4*)&W[(size_t)(k0 + wk) * 256 + col0 + wc];
        __syncthreads();
        As[lk + 0][lr] = a.x;
        As[lk + 1][lr] = a.y;
        As[lk + 2][lr] = a.z;
        As[lk + 3][lr] = a.w;
        *(float4*)&Ws[wk][wc] = w;
        __syncthreads();
#pragma unroll
        for (int kk = 0; kk < 16; kk++) {
            float4 av = *(const float4*)&As[kk][ty * 4];
            float4 wv = *(const float4*)&Ws[kk][tx * 4];
            acc[0][0] += av.x * wv.x; acc[0][1] += av.x * wv.y; acc[0][2] += av.x * wv.z; acc[0][3] += av.x * wv.w;
            acc[1][0] += av.y * wv.x; acc[1][1] += av.y * wv.y; acc[1][2] += av.y * wv.z; acc[1][3] += av.y * wv.w;
            acc[2][0] += av.z * wv.x; acc[2][1] += av.z * wv.y; acc[2][2] += av.z * wv.z; acc[2][3] += av.z * wv.w;
            acc[3][0] += av.w * wv.x; acc[3][1] += av.w * wv.y; acc[3][2] += av.w * wv.z; acc[3][3] += av.w * wv.w;
        }
    }

    float4 bv = *(const float4*)&bias[col0 + tx * 4];
#pragma unroll
    for (int r = 0; r < 4; r++) {
        float4 o;
        o.x = acc[r][0] + bv.x;
        o.y = acc[r][1] + bv.y;
        o.z = acc[r][2] + bv.z;
        o.w = acc[r][3] + bv.w;
        *(float4*)&C[(size_t)(row0 + ty * 4 + r) * 256 + col0 + tx * 4] = o;
    }
}

// ---------------- kNN: per-query top-16 by squared distance ----------------
__global__ void knn_kernel(const float* __restrict__ src,
                           const float* __restrict__ tgt,
                           int* __restrict__ knn_idx)
{
    __shared__ float dist[Mk];       // 16 KB
    __shared__ float rmin[128];
    __shared__ int   ridx[128];

    const int qid = blockIdx.x;      // 0..B*Nq-1
    const int b   = qid / Nq;
    const int tid = threadIdx.x;

    const float qx = src[(size_t)qid * 3 + 0];
    const float qy = src[(size_t)qid * 3 + 1];
    const float qz = src[(size_t)qid * 3 + 2];
    const float qq = qx * qx + qy * qy + qz * qz;
    const float* tb = tgt + (size_t)b * Mk * 3;

    for (int m = tid; m < Mk; m += 128) {
        float x = tb[(size_t)m * 3 + 0];
        float y = tb[(size_t)m * 3 + 1];
        float z = tb[(size_t)m * 3 + 2];
        float yy = x * x + y * y + z * z;
        float dot = qx * x + qy * y + qz * z;
        float sq = qq + yy - 2.f * dot;
        dist[m] = fmaxf(sq, 0.f);    // matches reference clamp (ordering-preserving)
    }
    __syncthreads();

    for (int it = 0; it < KNNk; it++) {
        float bm = CUDART_INF_F;
        int bi = Mk;
        for (int m = tid; m < Mk; m += 128) {
            float v = dist[m];
            if (v < bm) { bm = v; bi = m; }  // strict < keeps lowest index on ties
        }
        rmin[tid] = bm; ridx[tid] = bi;
        __syncthreads();
        for (int s = 64; s > 0; s >>= 1) {
            if (tid < s) {
                float v2 = rmin[tid + s]; int i2 = ridx[tid + s];
                if (v2 < rmin[tid] || (v2 == rmin[tid] && i2 < ridx[tid])) {
                    rmin[tid] = v2; ridx[tid] = i2;
                }
            }
            __syncthreads();
        }
        int w = ridx[0];
        if (tid == 0) {
            knn_idx[(size_t)qid * KNNk + it] = w;
            dist[w] = CUDART_INF_F;
        }
        __syncthreads();
    }
}

// ---------------- sparse attention: one block per query ----------------
__global__ void attn_kernel(const float* __restrict__ src_fea,
                            float* __restrict__ avg_attn)
{
    __shared__ int   sidx[KNNk];
    __shared__ float sq[Dd];
    __shared__ float sattn[Hh][KNNk];

    const int qid = blockIdx.x;
    const int b   = qid / Nq;
    const int tid = threadIdx.x;

    if (tid < KNNk) sidx[tid] = g_idx[(size_t)qid * KNNk + tid];
    sq[tid] = g_Q[(size_t)qid * Dd + tid];
    __syncthreads();

    if (tid < Hh * KNNk) {
        const int h = tid >> 4;
        const int j = tid & 15;
        const float* krow = &g_K[((size_t)b * Mk + sidx[j]) * Dd + h * DK];
        float s = 0.f;
#pragma unroll
        for (int d = 0; d < DK; d++) s += sq[h * DK + d] * krow[d];
        s *= 0.17677669529663687f;   // 32^-0.5

        // softmax over the 16-lane group (offsets 1..8 never cross the 16-lane half)
        float m = s;
#pragma unroll
        for (int o = 8; o > 0; o >>= 1) m = fmaxf(m, __shfl_xor_sync(0xFFFFFFFFu, m, o));
        float e = __expf(s - m);
        float sum = e;
#pragma unroll
        for (int o = 8; o > 0; o >>= 1) sum += __shfl_xor_sync(0xFFFFFFFFu, sum, o);
        sattn[h][j] = e / sum;
    }
    __syncthreads();

    // output: thread d accumulates over 16 neighbors
    {
        const int d = tid;
        const int h = d >> 5;
        float o = 0.f;
#pragma unroll
        for (int j = 0; j < KNNk; j++)
            o += sattn[h][j] * g_V[((size_t)b * Mk + sidx[j]) * Dd + d];
        g_X[(size_t)qid * Dd + d] = o + src_fea[(size_t)qid * Dd + d];
    }

    // avg_attn row: zero then scatter 16 values (barrier orders the writes)
    float* rowp = avg_attn + (size_t)qid * Mk;
    float4 z = make_float4(0.f, 0.f, 0.f, 0.f);
    for (int i = tid; i < Mk / 4; i += 256) ((float4*)rowp)[i] = z;
    __syncthreads();
    if (tid < KNNk) {
        float a = 0.f;
#pragma unroll
        for (int h = 0; h < Hh; h++) a += sattn[h][tid];
        rowp[sidx[tid]] = a * 0.125f;
    }
}

// ---------------- LayerNorm + ReLU: one block per row ----------------
__global__ void ln_relu_kernel(const float* __restrict__ T,
                               const float* __restrict__ gam,
                               const float* __restrict__ bet,
                               float* __restrict__ Hb)
{
    __shared__ float red[8];
    const int row = blockIdx.x;
    const int tid = threadIdx.x;

    float x = T[(size_t)row * Dd + tid];

    float s = x;
#pragma unroll
    for (int o = 16; o > 0; o >>= 1) s += __shfl_xor_sync(0xFFFFFFFFu, s, o);
    if ((tid & 31) == 0) red[tid >> 5] = s;
    __syncthreads();
    float tot = red[0] + red[1] + red[2] + red[3] + red[4] + red[5] + red[6] + red[7];
    float mu = tot * (1.f / 256.f);
    __syncthreads();

    float dx = x - mu;
    float s2 = dx * dx;
#pragma unroll
    for (int o = 16; o > 0; o >>= 1) s2 += __shfl_xor_sync(0xFFFFFFFFu, s2, o);
    if ((tid & 31) == 0) red[tid >> 5] = s2;
    __syncthreads();
    float tot2 = red[0] + red[1] + red[2] + red[3] + red[4] + red[5] + red[6] + red[7];
    float var = tot2 * (1.f / 256.f);

    float y = dx * rsqrtf(var + 1e-5f) * gam[tid] + bet[tid];
    Hb[(size_t)row * Dd + tid] = fmaxf(y, 0.f);
}

// ---------------- launch ----------------
extern "C" void kernel_launch(void* const* d_in, const int* in_sizes, int n_in,
                              void* d_out, int out_size)
{
    const float* src     = (const float*)d_in[0];
    const float* tgt     = (const float*)d_in[1];
    const float* src_fea = (const float*)d_in[2];
    const float* tgt_fea = (const float*)d_in[3];
    const float* Wq  = (const float*)d_in[4];  const float* bq  = (const float*)d_in[5];
    const float* Wk  = (const float*)d_in[6];  const float* bk  = (const float*)d_in[7];
    const float* Wv  = (const float*)d_in[8];  const float* bv  = (const float*)d_in[9];
    const float* Wo1 = (const float*)d_in[10]; const float* bo1 = (const float*)d_in[11];
    const float* lng = (const float*)d_in[12]; const float* lnb = (const float*)d_in[13];
    const float* Wo2 = (const float*)d_in[14]; const float* bo2 = (const float*)d_in[15];

    float* outp = (float*)d_out;
    float* upd  = outp;                              // [B,N,D]
    float* avg  = outp + (size_t)Bb * Nq * Dd;       // [B,N,M]

    float *pQ, *pK, *pV, *pX, *pT, *pHb; int* pIdx;
    cudaGetSymbolAddress((void**)&pQ,  g_Q);
    cudaGetSymbolAddress((void**)&pK,  g_K);
    cudaGetSymbolAddress((void**)&pV,  g_V);
    cudaGetSymbolAddress((void**)&pX,  g_X);
    cudaGetSymbolAddress((void**)&pT,  g_T);
    cudaGetSymbolAddress((void**)&pHb, g_Hb);
    cudaGetSymbolAddress((void**)&pIdx, g_idx);

    // projections
    gemm_bias_kernel<<<dim3(4, (Bb * Nq) / 64), 256>>>(src_fea, Wq, bq, pQ);
    gemm_bias_kernel<<<dim3(4, (Bb * Mk) / 64), 256>>>(tgt_fea, Wk, bk, pK);
    gemm_bias_kernel<<<dim3(4, (Bb * Mk) / 64), 256>>>(tgt_fea, Wv, bv, pV);

    // kNN selection (independent of projections; runs in the same stream order)
    knn_kernel<<<Bb * Nq, 128>>>(src, tgt, pIdx);

    // sparse attention + residual + avg_attn output
    attn_kernel<<<Bb * Nq, 256>>>(src_fea, avg);

    // output MLP: LN(x@Wo1+bo1) -> relu -> @Wo2+bo2
    gemm_bias_kernel<<<dim3(4, (Bb * Nq) / 64), 256>>>(pX, Wo1, bo1, pT);
    ln_relu_kernel<<<Bb * Nq, 256>>>(pT, lng, lnb, pHb);
    gemm_bias_kernel<<<dim3(4, (Bb * Nq) / 64), 256>>>(pHb, Wo2, bo2, upd);
}

// round 2
// speedup vs baseline: 1.1577x; 1.1577x over previous
#include <cuda_runtime.h>
#include <math_constants.h>
#include <cstdint>

#define Bb   2
#define Nq   2048
#define Mk   4096
#define Dd   256
#define Hh   8
#define DK   32
#define KNNk 16

// ---------------- scratch (static device globals; no allocation) ----------------
__device__ float g_Q[(size_t)Bb * Nq * Dd];
__device__ float g_K[(size_t)Bb * Mk * Dd];
__device__ float g_V[(size_t)Bb * Mk * Dd];
__device__ float g_X[(size_t)Bb * Nq * Dd];
__device__ float g_T[(size_t)Bb * Nq * Dd];
__device__ float g_Hb[(size_t)Bb * Nq * Dd];
__device__ int   g_idx[(size_t)Bb * Nq * KNNk];

// ======================= GEMM (single W): C[rows,256] = A @ W + b =======================
// 128x64 tile, 256 threads, 8x4 microtile, k-chunk 16.
__global__ __launch_bounds__(256) void gemm_bias_kernel(
    const float* __restrict__ A, const float* __restrict__ W,
    const float* __restrict__ bias, float* __restrict__ C)
{
    __shared__ float As[16][132];
    __shared__ float Ws[16][68];

    const int tid  = threadIdx.x;
    const int row0 = blockIdx.y * 128;
    const int col0 = blockIdx.x * 64;
    const int tx = tid & 15;        // col group (4 cols)
    const int ty = tid >> 4;        // row group (8 rows)
    const int wk = tid >> 4;
    const int wc = (tid & 15) * 4;

    float acc[8][4];
#pragma unroll
    for (int r = 0; r < 8; r++)
#pragma unroll
        for (int c = 0; c < 4; c++) acc[r][c] = 0.f;

    for (int k0 = 0; k0 < 256; k0 += 16) {
        float4 a[2];
#pragma unroll
        for (int u = 0; u < 2; u++) {
            int idx = tid * 2 + u;
            a[u] = *(const float4*)&A[(size_t)(row0 + (idx >> 2)) * 256 + k0 + (idx & 3) * 4];
        }
        float4 w = *(const float4*)&W[(size_t)(k0 + wk) * 256 + col0 + wc];
        __syncthreads();
#pragma unroll
        for (int u = 0; u < 2; u++) {
            int idx = tid * 2 + u;
            int rr = idx >> 2, lk = (idx & 3) * 4;
            As[lk + 0][rr] = a[u].x;
            As[lk + 1][rr] = a[u].y;
            As[lk + 2][rr] = a[u].z;
            As[lk + 3][rr] = a[u].w;
        }
        *(float4*)&Ws[wk][wc] = w;
        __syncthreads();
#pragma unroll
        for (int kk = 0; kk < 16; kk++) {
            float4 a0 = *(const float4*)&As[kk][ty * 8];
            float4 a1 = *(const float4*)&As[kk][ty * 8 + 4];
            float4 wv = *(const float4*)&Ws[kk][tx * 4];
            float ar[8] = {a0.x, a0.y, a0.z, a0.w, a1.x, a1.y, a1.z, a1.w};
#pragma unroll
            for (int r = 0; r < 8; r++) {
                acc[r][0] += ar[r] * wv.x;
                acc[r][1] += ar[r] * wv.y;
                acc[r][2] += ar[r] * wv.z;
                acc[r][3] += ar[r] * wv.w;
            }
        }
    }

    float4 bv = *(const float4*)&bias[col0 + tx * 4];
#pragma unroll
    for (int r = 0; r < 8; r++) {
        float4 o;
        o.x = acc[r][0] + bv.x; o.y = acc[r][1] + bv.y;
        o.z = acc[r][2] + bv.z; o.w = acc[r][3] + bv.w;
        *(float4*)&C[(size_t)(row0 + ty * 8 + r) * 256 + col0 + tx * 4] = o;
    }
}

// ======================= Dual GEMM: K and V share the A tile =======================
__global__ __launch_bounds__(256) void gemm_dual_kernel(
    const float* __restrict__ A,
    const float* __restrict__ WK, const float* __restrict__ bK,
    const float* __restrict__ WV, const float* __restrict__ bV,
    float* __restrict__ CK, float* __restrict__ CV)
{
    __shared__ float As[16][132];
    __shared__ float WsK[16][68];
    __shared__ float WsV[16][68];

    const int tid  = threadIdx.x;
    const int row0 = blockIdx.y * 128;
    const int col0 = blockIdx.x * 64;
    const int tx = tid & 15;
    const int ty = tid >> 4;
    const int wk = tid >> 4;
    const int wc = (tid & 15) * 4;

    float accK[8][4], accV[8][4];
#pragma unroll
    for (int r = 0; r < 8; r++)
#pragma unroll
        for (int c = 0; c < 4; c++) { accK[r][c] = 0.f; accV[r][c] = 0.f; }

    for (int k0 = 0; k0 < 256; k0 += 16) {
        float4 a[2];
#pragma unroll
        for (int u = 0; u < 2; u++) {
            int idx = tid * 2 + u;
            a[u] = *(const float4*)&A[(size_t)(row0 + (idx >> 2)) * 256 + k0 + (idx & 3) * 4];
        }
        float4 wk4 = *(const float4*)&WK[(size_t)(k0 + wk) * 256 + col0 + wc];
        float4 wv4 = *(const float4*)&WV[(size_t)(k0 + wk) * 256 + col0 + wc];
        __syncthreads();
#pragma unroll
        for (int u = 0; u < 2; u++) {
            int idx = tid * 2 + u;
            int rr = idx >> 2, lk = (idx & 3) * 4;
            As[lk + 0][rr] = a[u].x;
            As[lk + 1][rr] = a[u].y;
            As[lk + 2][rr] = a[u].z;
            As[lk + 3][rr] = a[u].w;
        }
        *(float4*)&WsK[wk][wc] = wk4;
        *(float4*)&WsV[wk][wc] = wv4;
        __syncthreads();
#pragma unroll
        for (int kk = 0; kk < 16; kk++) {
            float4 a0 = *(const float4*)&As[kk][ty * 8];
            float4 a1 = *(const float4*)&As[kk][ty * 8 + 4];
            float4 wKv = *(const float4*)&WsK[kk][tx * 4];
            float4 wVv = *(const float4*)&WsV[kk][tx * 4];
            float ar[8] = {a0.x, a0.y, a0.z, a0.w, a1.x, a1.y, a1.z, a1.w};
#pragma unroll
            for (int r = 0; r < 8; r++) {
                accK[r][0] += ar[r] * wKv.x;
                accK[r][1] += ar[r] * wKv.y;
                accK[r][2] += ar[r] * wKv.z;
                accK[r][3] += ar[r] * wKv.w;
                accV[r][0] += ar[r] * wVv.x;
                accV[r][1] += ar[r] * wVv.y;
                accV[r][2] += ar[r] * wVv.z;
                accV[r][3] += ar[r] * wVv.w;
            }
        }
    }

    float4 bKv = *(const float4*)&bK[col0 + tx * 4];
    float4 bVv = *(const float4*)&bV[col0 + tx * 4];
#pragma unroll
    for (int r = 0; r < 8; r++) {
        size_t off = (size_t)(row0 + ty * 8 + r) * 256 + col0 + tx * 4;
        float4 ok, ov;
        ok.x = accK[r][0] + bKv.x; ok.y = accK[r][1] + bKv.y;
        ok.z = accK[r][2] + bKv.z; ok.w = accK[r][3] + bKv.w;
        ov.x = accV[r][0] + bVv.x; ov.y = accV[r][1] + bVv.y;
        ov.z = accV[r][2] + bVv.z; ov.w = accV[r][3] + bVv.w;
        *(float4*)&CK[off] = ok;
        *(float4*)&CV[off] = ov;
    }
}

// ======================= kNN: lazy-rescan top-16 =======================
// Thread t owns strided elements {t, t+128, ...}. Per extraction: one warp
// argmins the 128 cached local minima; only the winner's owner rescans.
__global__ __launch_bounds__(128) void knn_kernel(
    const float* __restrict__ src, const float* __restrict__ tgt,
    int* __restrict__ knn_idx)
{
    __shared__ float dist[Mk];
    __shared__ float lmin[128];
    __shared__ int   lidx[128];
    __shared__ int   s_win;

    const int qid = blockIdx.x;
    const int b   = qid / Nq;
    const int tid = threadIdx.x;

    const float qx = src[(size_t)qid * 3 + 0];
    const float qy = src[(size_t)qid * 3 + 1];
    const float qz = src[(size_t)qid * 3 + 2];
    const float qq = qx * qx + qy * qy + qz * qz;
    const float* tb = tgt + (size_t)b * Mk * 3;

    float bm = CUDART_INF_F;
    int   bi = Mk;
    for (int m = tid; m < Mk; m += 128) {
        float x = tb[(size_t)m * 3 + 0];
        float y = tb[(size_t)m * 3 + 1];
        float z = tb[(size_t)m * 3 + 2];
        float sq = fmaxf(qq + (x * x + y * y + z * z) - 2.f * (qx * x + qy * y + qz * z), 0.f);
        dist[m] = sq;
        if (sq < bm) { bm = sq; bi = m; }   // strict < keeps lowest index on ties
    }
    lmin[tid] = bm; lidx[tid] = bi;
    __syncthreads();

    for (int it = 0; it < KNNk; it++) {
        if (tid < 32) {
            float v = lmin[tid]; int ix = lidx[tid];
#pragma unroll
            for (int j = 32; j < 128; j += 32) {
                float v2 = lmin[tid + j]; int i2 = lidx[tid + j];
                if (v2 < v || (v2 == v && i2 < ix)) { v = v2; ix = i2; }
            }
#pragma unroll
            for (int o = 16; o > 0; o >>= 1) {
                float v2 = __shfl_xor_sync(0xFFFFFFFFu, v, o);
                int   i2 = __shfl_xor_sync(0xFFFFFFFFu, ix, o);
                if (v2 < v || (v2 == v && i2 < ix)) { v = v2; ix = i2; }
            }
            if (tid == 0) {
                s_win = ix;
                knn_idx[(size_t)qid * KNNk + it] = ix;
                dist[ix] = CUDART_INF_F;
            }
        }
        __syncthreads();
        if (it < KNNk - 1) {
            int owner = s_win & 127;
            if (tid == owner) {
                float nb = CUDART_INF_F; int ni = Mk;
                for (int m = tid; m < Mk; m += 128) {
                    float v = dist[m];
                    if (v < nb) { nb = v; ni = m; }
                }
                lmin[tid] = nb; lidx[tid] = ni;
            }
            __syncthreads();
        }
    }
}

// ======================= sparse attention =======================
__global__ __launch_bounds__(256) void attn_kernel(const float* __restrict__ src_fea,
                                                   float* __restrict__ avg_attn)
{
    __shared__ int   sidx[KNNk];
    __shared__ float sq[Dd];
    __shared__ float sattn[Hh][KNNk];

    const int qid = blockIdx.x;
    const int b   = qid / Nq;
    const int tid = threadIdx.x;

    if (tid < KNNk) sidx[tid] = g_idx[(size_t)qid * KNNk + tid];
    sq[tid] = g_Q[(size_t)qid * Dd + tid];
    __syncthreads();

    if (tid < Hh * KNNk) {
        const int h = tid >> 4;
        const int j = tid & 15;
        const float* krow = &g_K[((size_t)b * Mk + sidx[j]) * Dd + h * DK];
        float s = 0.f;
#pragma unroll
        for (int d = 0; d < DK; d++) s += sq[h * DK + d] * krow[d];
        s *= 0.17677669529663687f;   // 32^-0.5

        float m = s;
#pragma unroll
        for (int o = 8; o > 0; o >>= 1) m = fmaxf(m, __shfl_xor_sync(0xFFFFFFFFu, m, o));
        float e = __expf(s - m);
        float sum = e;
#pragma unroll
        for (int o = 8; o > 0; o >>= 1) sum += __shfl_xor_sync(0xFFFFFFFFu, sum, o);
        sattn[h][j] = e / sum;
    }
    __syncthreads();

    {
        const int d = tid;
        const int h = d >> 5;
        float o = 0.f;
#pragma unroll
        for (int j = 0; j < KNNk; j++)
            o += sattn[h][j] * g_V[((size_t)b * Mk + sidx[j]) * Dd + d];
        g_X[(size_t)qid * Dd + d] = o + src_fea[(size_t)qid * Dd + d];
    }

    float* rowp = avg_attn + (size_t)qid * Mk;
    float4 z = make_float4(0.f, 0.f, 0.f, 0.f);
    for (int i = tid; i < Mk / 4; i += 256) ((float4*)rowp)[i] = z;
    __syncthreads();
    if (tid < KNNk) {
        float a = 0.f;
#pragma unroll
        for (int h = 0; h < Hh; h++) a += sattn[h][tid];
        rowp[sidx[tid]] = a * 0.125f;
    }
}

// ======================= LayerNorm + ReLU =======================
__global__ __launch_bounds__(256) void ln_relu_kernel(
    const float* __restrict__ T, const float* __restrict__ gam,
    const float* __restrict__ bet, float* __restrict__ Hb)
{
    __shared__ float red[8];
    const int row = blockIdx.x;
    const int tid = threadIdx.x;

    float x = T[(size_t)row * Dd + tid];

    float s = x;
#pragma unroll
    for (int o = 16; o > 0; o >>= 1) s += __shfl_xor_sync(0xFFFFFFFFu, s, o);
    if ((tid & 31) == 0) red[tid >> 5] = s;
    __syncthreads();
    float mu = (red[0] + red[1] + red[2] + red[3] + red[4] + red[5] + red[6] + red[7]) * (1.f / 256.f);
    __syncthreads();

    float dx = x - mu;
    float s2 = dx * dx;
#pragma unroll
    for (int o = 16; o > 0; o >>= 1) s2 += __shfl_xor_sync(0xFFFFFFFFu, s2, o);
    if ((tid & 31) == 0) red[tid >> 5] = s2;
    __syncthreads();
    float var = (red[0] + red[1] + red[2] + red[3] + red[4] + red[5] + red[6] + red[7]) * (1.f / 256.f);

    float y = dx * rsqrtf(var + 1e-5f) * gam[tid] + bet[tid];
    Hb[(size_t)row * Dd + tid] = fmaxf(y, 0.f);
}

// ======================= launch =======================
extern "C" void kernel_launch(void* const* d_in, const int* in_sizes, int n_in,
                              void* d_out, int out_size)
{
    const float* src     = (const float*)d_in[0];
    const float* tgt     = (const float*)d_in[1];
    const float* src_fea = (const float*)d_in[2];
    const float* tgt_fea = (const float*)d_in[3];
    const float* Wq  = (const float*)d_in[4];  const float* bq  = (const float*)d_in[5];
    const float* Wk  = (const float*)d_in[6];  const float* bk  = (const float*)d_in[7];
    const float* Wv  = (const float*)d_in[8];  const float* bv  = (const float*)d_in[9];
    const float* Wo1 = (const float*)d_in[10]; const float* bo1 = (const float*)d_in[11];
    const float* lng = (const float*)d_in[12]; const float* lnb = (const float*)d_in[13];
    const float* Wo2 = (const float*)d_in[14]; const float* bo2 = (const float*)d_in[15];

    float* outp = (float*)d_out;
    float* upd  = outp;
    float* avg  = outp + (size_t)Bb * Nq * Dd;

    float *pQ, *pK, *pV, *pX, *pT, *pHb; int* pIdx;
    cudaGetSymbolAddress((void**)&pQ,  g_Q);
    cudaGetSymbolAddress((void**)&pK,  g_K);
    cudaGetSymbolAddress((void**)&pV,  g_V);
    cudaGetSymbolAddress((void**)&pX,  g_X);
    cudaGetSymbolAddress((void**)&pT,  g_T);
    cudaGetSymbolAddress((void**)&pHb, g_Hb);
    cudaGetSymbolAddress((void**)&pIdx, g_idx);

    // kNN first (independent): overlaps nothing but keeps critical path clean
    knn_kernel<<<Bb * Nq, 128>>>(src, tgt, pIdx);

    // projections
    gemm_bias_kernel<<<dim3(4, (Bb * Nq) / 128), 256>>>(src_fea, Wq, bq, pQ);
    gemm_dual_kernel<<<dim3(4, (Bb * Mk) / 128), 256>>>(tgt_fea, Wk, bk, Wv, bv, pK, pV);

    // sparse attention + residual + avg_attn
    attn_kernel<<<Bb * Nq, 256>>>(src_fea, avg);

    // output MLP
    gemm_bias_kernel<<<dim3(4, (Bb * Nq) / 128), 256>>>(pX, Wo1, bo1, pT);
    ln_relu_kernel<<<Bb * Nq, 256>>>(pT, lng, lnb, pHb);
    gemm_bias_kernel<<<dim3(4, (Bb * Nq) / 128), 256>>>(pHb, Wo2, bo2, upd);
}

// round 3
// speedup vs baseline: 1.3535x; 1.1692x over previous
#include <cuda_runtime.h>
#include <math_constants.h>
#include <cstdint>

#define Bb   2
#define Nq   2048
#define Mk   4096
#define Dd   256
#define Hh   8
#define DK   32
#define KNNk 16

// ---------------- scratch (static device globals; no allocation) ----------------
__device__ float g_Q[(size_t)Bb * Nq * Dd];
__device__ float g_K[(size_t)Bb * Mk * Dd];
__device__ float g_V[(size_t)Bb * Mk * Dd];
__device__ float g_X[(size_t)Bb * Nq * Dd];
__device__ float g_T[(size_t)Bb * Nq * Dd];
__device__ float g_Hb[(size_t)Bb * Nq * Dd];
__device__ int   g_idx[(size_t)Bb * Nq * KNNk];

// ======================= GEMM (single W): C[rows,256] = A @ W + b =======================
__global__ __launch_bounds__(256) void gemm_bias_kernel(
    const float* __restrict__ A, const float* __restrict__ W,
    const float* __restrict__ bias, float* __restrict__ C)
{
    __shared__ float As[16][132];
    __shared__ float Ws[16][68];

    const int tid  = threadIdx.x;
    const int row0 = blockIdx.y * 128;
    const int col0 = blockIdx.x * 64;
    const int tx = tid & 15;
    const int ty = tid >> 4;
    const int wk = tid >> 4;
    const int wc = (tid & 15) * 4;

    float acc[8][4];
#pragma unroll
    for (int r = 0; r < 8; r++)
#pragma unroll
        for (int c = 0; c < 4; c++) acc[r][c] = 0.f;

    for (int k0 = 0; k0 < 256; k0 += 16) {
        float4 a[2];
#pragma unroll
        for (int u = 0; u < 2; u++) {
            int idx = tid * 2 + u;
            a[u] = *(const float4*)&A[(size_t)(row0 + (idx >> 2)) * 256 + k0 + (idx & 3) * 4];
        }
        float4 w = *(const float4*)&W[(size_t)(k0 + wk) * 256 + col0 + wc];
        __syncthreads();
#pragma unroll
        for (int u = 0; u < 2; u++) {
            int idx = tid * 2 + u;
            int rr = idx >> 2, lk = (idx & 3) * 4;
            As[lk + 0][rr] = a[u].x;
            As[lk + 1][rr] = a[u].y;
            As[lk + 2][rr] = a[u].z;
            As[lk + 3][rr] = a[u].w;
        }
        *(float4*)&Ws[wk][wc] = w;
        __syncthreads();
#pragma unroll
        for (int kk = 0; kk < 16; kk++) {
            float4 a0 = *(const float4*)&As[kk][ty * 8];
            float4 a1 = *(const float4*)&As[kk][ty * 8 + 4];
            float4 wv = *(const float4*)&Ws[kk][tx * 4];
            float ar[8] = {a0.x, a0.y, a0.z, a0.w, a1.x, a1.y, a1.z, a1.w};
#pragma unroll
            for (int r = 0; r < 8; r++) {
                acc[r][0] += ar[r] * wv.x;
                acc[r][1] += ar[r] * wv.y;
                acc[r][2] += ar[r] * wv.z;
                acc[r][3] += ar[r] * wv.w;
            }
        }
    }

    float4 bv = *(const float4*)&bias[col0 + tx * 4];
#pragma unroll
    for (int r = 0; r < 8; r++) {
        float4 o;
        o.x = acc[r][0] + bv.x; o.y = acc[r][1] + bv.y;
        o.z = acc[r][2] + bv.z; o.w = acc[r][3] + bv.w;
        *(float4*)&C[(size_t)(row0 + ty * 8 + r) * 256 + col0 + tx * 4] = o;
    }
}

// ======================= Dual GEMM: K and V share the A tile =======================
__global__ __launch_bounds__(256) void gemm_dual_kernel(
    const float* __restrict__ A,
    const float* __restrict__ WK, const float* __restrict__ bK,
    const float* __restrict__ WV, const float* __restrict__ bV,
    float* __restrict__ CK, float* __restrict__ CV)
{
    __shared__ float As[16][132];
    __shared__ float WsK[16][68];
    __shared__ float WsV[16][68];

    const int tid  = threadIdx.x;
    const int row0 = blockIdx.y * 128;
    const int col0 = blockIdx.x * 64;
    const int tx = tid & 15;
    const int ty = tid >> 4;
    const int wk = tid >> 4;
    const int wc = (tid & 15) * 4;

    float accK[8][4], accV[8][4];
#pragma unroll
    for (int r = 0; r < 8; r++)
#pragma unroll
        for (int c = 0; c < 4; c++) { accK[r][c] = 0.f; accV[r][c] = 0.f; }

    for (int k0 = 0; k0 < 256; k0 += 16) {
        float4 a[2];
#pragma unroll
        for (int u = 0; u < 2; u++) {
            int idx = tid * 2 + u;
            a[u] = *(const float4*)&A[(size_t)(row0 + (idx >> 2)) * 256 + k0 + (idx & 3) * 4];
        }
        float4 wk4 = *(const float4*)&WK[(size_t)(k0 + wk) * 256 + col0 + wc];
        float4 wv4 = *(const float4*)&WV[(size_t)(k0 + wk) * 256 + col0 + wc];
        __syncthreads();
#pragma unroll
        for (int u = 0; u < 2; u++) {
            int idx = tid * 2 + u;
            int rr = idx >> 2, lk = (idx & 3) * 4;
            As[lk + 0][rr] = a[u].x;
            As[lk + 1][rr] = a[u].y;
            As[lk + 2][rr] = a[u].z;
            As[lk + 3][rr] = a[u].w;
        }
        *(float4*)&WsK[wk][wc] = wk4;
        *(float4*)&WsV[wk][wc] = wv4;
        __syncthreads();
#pragma unroll
        for (int kk = 0; kk < 16; kk++) {
            float4 a0 = *(const float4*)&As[kk][ty * 8];
            float4 a1 = *(const float4*)&As[kk][ty * 8 + 4];
            float4 wKv = *(const float4*)&WsK[kk][tx * 4];
            float4 wVv = *(const float4*)&WsV[kk][tx * 4];
            float ar[8] = {a0.x, a0.y, a0.z, a0.w, a1.x, a1.y, a1.z, a1.w};
#pragma unroll
            for (int r = 0; r < 8; r++) {
                accK[r][0] += ar[r] * wKv.x;
                accK[r][1] += ar[r] * wKv.y;
                accK[r][2] += ar[r] * wKv.z;
                accK[r][3] += ar[r] * wKv.w;
                accV[r][0] += ar[r] * wVv.x;
                accV[r][1] += ar[r] * wVv.y;
                accV[r][2] += ar[r] * wVv.z;
                accV[r][3] += ar[r] * wVv.w;
            }
        }
    }

    float4 bKv = *(const float4*)&bK[col0 + tx * 4];
    float4 bVv = *(const float4*)&bV[col0 + tx * 4];
#pragma unroll
    for (int r = 0; r < 8; r++) {
        size_t off = (size_t)(row0 + ty * 8 + r) * 256 + col0 + tx * 4;
        float4 ok, ov;
        ok.x = accK[r][0] + bKv.x; ok.y = accK[r][1] + bKv.y;
        ok.z = accK[r][2] + bKv.z; ok.w = accK[r][3] + bKv.w;
        ov.x = accV[r][0] + bVv.x; ov.y = accV[r][1] + bVv.y;
        ov.z = accV[r][2] + bVv.z; ov.w = accV[r][3] + bVv.w;
        *(float4*)&CK[off] = ok;
        *(float4*)&CV[off] = ov;
    }
}

// ======================= kNN: lazy-rescan top-16 =======================
__global__ __launch_bounds__(128) void knn_kernel(
    const float* __restrict__ src, const float* __restrict__ tgt,
    int* __restrict__ knn_idx)
{
    __shared__ float dist[Mk];
    __shared__ float lmin[128];
    __shared__ int   lidx[128];
    __shared__ int   s_win;

    const int qid = blockIdx.x;
    const int b   = qid / Nq;
    const int tid = threadIdx.x;

    const float qx = src[(size_t)qid * 3 + 0];
    const float qy = src[(size_t)qid * 3 + 1];
    const float qz = src[(size_t)qid * 3 + 2];
    const float qq = qx * qx + qy * qy + qz * qz;
    const float* tb = tgt + (size_t)b * Mk * 3;

    float bm = CUDART_INF_F;
    int   bi = Mk;
    for (int m = tid; m < Mk; m += 128) {
        float x = tb[(size_t)m * 3 + 0];
        float y = tb[(size_t)m * 3 + 1];
        float z = tb[(size_t)m * 3 + 2];
        float sq = fmaxf(qq + (x * x + y * y + z * z) - 2.f * (qx * x + qy * y + qz * z), 0.f);
        dist[m] = sq;
        if (sq < bm) { bm = sq; bi = m; }
    }
    lmin[tid] = bm; lidx[tid] = bi;
    __syncthreads();

    for (int it = 0; it < KNNk; it++) {
        if (tid < 32) {
            float v = lmin[tid]; int ix = lidx[tid];
#pragma unroll
            for (int j = 32; j < 128; j += 32) {
                float v2 = lmin[tid + j]; int i2 = lidx[tid + j];
                if (v2 < v || (v2 == v && i2 < ix)) { v = v2; ix = i2; }
            }
#pragma unroll
            for (int o = 16; o > 0; o >>= 1) {
                float v2 = __shfl_xor_sync(0xFFFFFFFFu, v, o);
                int   i2 = __shfl_xor_sync(0xFFFFFFFFu, ix, o);
                if (v2 < v || (v2 == v && i2 < ix)) { v = v2; ix = i2; }
            }
            if (tid == 0) {
                s_win = ix;
                knn_idx[(size_t)qid * KNNk + it] = ix;
                dist[ix] = CUDART_INF_F;
            }
        }
        __syncthreads();
        if (it < KNNk - 1) {
            int owner = s_win & 127;
            if (tid == owner) {
                float nb = CUDART_INF_F; int ni = Mk;
                for (int m = tid; m < Mk; m += 128) {
                    float v = dist[m];
                    if (v < nb) { nb = v; ni = m; }
                }
                lmin[tid] = nb; lidx[tid] = ni;
            }
            __syncthreads();
        }
    }
}

// ======================= sparse attention (shared K/V tiles) =======================
#define KSTRIDE 261   // odd stride: 16 j-rows map to 16 distinct banks

__global__ __launch_bounds__(256) void attn_kernel(const float* __restrict__ src_fea,
                                                   float* __restrict__ avg_attn)
{
    __shared__ int   sidx[KNNk];
    __shared__ float sq[Dd];
    __shared__ float sattn[Hh][KNNk];
    __shared__ float sK[KNNk][KSTRIDE];
    __shared__ float sV[KNNk][KSTRIDE];

    const int qid = blockIdx.x;
    const int b   = qid / Nq;
    const int tid = threadIdx.x;

    if (tid < KNNk) sidx[tid] = g_idx[(size_t)qid * KNNk + tid];
    sq[tid] = g_Q[(size_t)qid * Dd + tid];
    __syncthreads();

    // cooperative coalesced gather of 16 K rows and 16 V rows (float4)
    {
        const int c4  = tid & 63;          // float4 column 0..63
        const int rg  = tid >> 6;          // row group 0..3
#pragma unroll
        for (int it = 0; it < 4; it++) {
            const int r = rg + it * 4;
            const size_t rowoff = ((size_t)b * Mk + sidx[r]) * Dd + c4 * 4;
            float4 kv = *(const float4*)&g_K[rowoff];
            float4 vv = *(const float4*)&g_V[rowoff];
            sK[r][c4 * 4 + 0] = kv.x; sK[r][c4 * 4 + 1] = kv.y;
            sK[r][c4 * 4 + 2] = kv.z; sK[r][c4 * 4 + 3] = kv.w;
            sV[r][c4 * 4 + 0] = vv.x; sV[r][c4 * 4 + 1] = vv.y;
            sV[r][c4 * 4 + 2] = vv.z; sV[r][c4 * 4 + 3] = vv.w;
        }
    }
    __syncthreads();

    // scores + softmax: 128 threads, one per (h, j)
    if (tid < Hh * KNNk) {
        const int h = tid >> 4;
        const int j = tid & 15;
        float s = 0.f;
#pragma unroll
        for (int d = 0; d < DK; d++) s += sq[h * DK + d] * sK[j][h * DK + d];
        s *= 0.17677669529663687f;   // 32^-0.5

        float m = s;
#pragma unroll
        for (int o = 8; o > 0; o >>= 1) m = fmaxf(m, __shfl_xor_sync(0xFFFFFFFFu, m, o));
        float e = __expf(s - m);
        float sum = e;
#pragma unroll
        for (int o = 8; o > 0; o >>= 1) sum += __shfl_xor_sync(0xFFFFFFFFu, sum, o);
        sattn[h][j] = e / sum;
    }
    __syncthreads();

    // output: thread d accumulates over 16 neighbors from shared V
    {
        const int d = tid;
        const int h = d >> 5;
        float o = 0.f;
#pragma unroll
        for (int j = 0; j < KNNk; j++)
            o += sattn[h][j] * sV[j][d];
        g_X[(size_t)qid * Dd + d] = o + src_fea[(size_t)qid * Dd + d];
    }

    // avg_attn row: zero then scatter 16 values
    float* rowp = avg_attn + (size_t)qid * Mk;
    float4 z = make_float4(0.f, 0.f, 0.f, 0.f);
#pragma unroll
    for (int i = 0; i < 4; i++) ((float4*)rowp)[tid + i * 256] = z;
    __syncthreads();
    if (tid < KNNk) {
        float a = 0.f;
#pragma unroll
        for (int h = 0; h < Hh; h++) a += sattn[h][tid];
        rowp[sidx[tid]] = a * 0.125f;
    }
}

// ======================= LayerNorm + ReLU =======================
__global__ __launch_bounds__(256) void ln_relu_kernel(
    const float* __restrict__ T, const float* __restrict__ gam,
    const float* __restrict__ bet, float* __restrict__ Hb)
{
    __shared__ float red[8];
    const int row = blockIdx.x;
    const int tid = threadIdx.x;

    float x = T[(size_t)row * Dd + tid];

    float s = x;
#pragma unroll
    for (int o = 16; o > 0; o >>= 1) s += __shfl_xor_sync(0xFFFFFFFFu, s, o);
    if ((tid & 31) == 0) red[tid >> 5] = s;
    __syncthreads();
    float mu = (red[0] + red[1] + red[2] + red[3] + red[4] + red[5] + red[6] + red[7]) * (1.f / 256.f);
    __syncthreads();

    float dx = x - mu;
    float s2 = dx * dx;
#pragma unroll
    for (int o = 16; o > 0; o >>= 1) s2 += __shfl_xor_sync(0xFFFFFFFFu, s2, o);
    if ((tid & 31) == 0) red[tid >> 5] = s2;
    __syncthreads();
    float var = (red[0] + red[1] + red[2] + red[3] + red[4] + red[5] + red[6] + red[7]) * (1.f / 256.f);

    float y = dx * rsqrtf(var + 1e-5f) * gam[tid] + bet[tid];
    Hb[(size_t)row * Dd + tid] = fmaxf(y, 0.f);
}

// ======================= launch =======================
extern "C" void kernel_launch(void* const* d_in, const int* in_sizes, int n_in,
                              void* d_out, int out_size)
{
    const float* src     = (const float*)d_in[0];
    const float* tgt     = (const float*)d_in[1];
    const float* src_fea = (const float*)d_in[2];
    const float* tgt_fea = (const float*)d_in[3];
    const float* Wq  = (const float*)d_in[4];  const float* bq  = (const float*)d_in[5];
    const float* Wk  = (const float*)d_in[6];  const float* bk  = (const float*)d_in[7];
    const float* Wv  = (const float*)d_in[8];  const float* bv  = (const float*)d_in[9];
    const float* Wo1 = (const float*)d_in[10]; const float* bo1 = (const float*)d_in[11];
    const float* lng = (const float*)d_in[12]; const float* lnb = (const float*)d_in[13];
    const float* Wo2 = (const float*)d_in[14]; const float* bo2 = (const float*)d_in[15];

    float* outp = (float*)d_out;
    float* upd  = outp;
    float* avg  = outp + (size_t)Bb * Nq * Dd;

    float *pQ, *pK, *pV, *pX, *pT, *pHb; int* pIdx;
    cudaGetSymbolAddress((void**)&pQ,  g_Q);
    cudaGetSymbolAddress((void**)&pK,  g_K);
    cudaGetSymbolAddress((void**)&pV,  g_V);
    cudaGetSymbolAddress((void**)&pX,  g_X);
    cudaGetSymbolAddress((void**)&pT,  g_T);
    cudaGetSymbolAddress((void**)&pHb, g_Hb);
    cudaGetSymbolAddress((void**)&pIdx, g_idx);

    knn_kernel<<<Bb * Nq, 128>>>(src, tgt, pIdx);

    gemm_bias_kernel<<<dim3(4, (Bb * Nq) / 128), 256>>>(src_fea, Wq, bq, pQ);
    gemm_dual_kernel<<<dim3(4, (Bb * Mk) / 128), 256>>>(tgt_fea, Wk, bk, Wv, bv, pK, pV);

    attn_kernel<<<Bb * Nq, 256>>>(src_fea, avg);

    gemm_bias_kernel<<<dim3(4, (Bb * Nq) / 128), 256>>>(pX, Wo1, bo1, pT);
    ln_relu_kernel<<<Bb * Nq, 256>>>(pT, lng, lnb, pHb);
    gemm_bias_kernel<<<dim3(4, (Bb * Nq) / 128), 256>>>(pHb, Wo2, bo2, upd);
}

// round 4
// speedup vs baseline: 2.1878x; 1.6164x over previous
#include <cuda_runtime.h>
#include <math_constants.h>
#include <cstdint>

#define Bb   2
#define Nq   2048
#define Mk   4096
#define Dd   256
#define Hh   8
#define DK   32
#define KNNk 16

// ---------------- scratch ----------------
__device__ float g_Q[(size_t)Bb * Nq * Dd];
__device__ float g_K[(size_t)Bb * Mk * Dd];
__device__ float g_V[(size_t)Bb * Mk * Dd];
__device__ float g_X[(size_t)Bb * Nq * Dd];
__device__ float g_T[(size_t)Bb * Nq * Dd];
__device__ float g_Hb[(size_t)Bb * Nq * Dd];
__device__ int   g_idx[(size_t)Bb * Nq * KNNk];

// ---------------- tf32 helpers ----------------
__device__ __forceinline__ uint32_t f2tf32(float f) {
    uint32_t r;
    asm("cvt.rna.tf32.f32 %0, %1;" : "=r"(r) : "f"(f));
    return r;
}
__device__ __forceinline__ void mma_tf32(float c[4], uint32_t a0, uint32_t a1,
                                         uint32_t a2, uint32_t a3,
                                         uint32_t b0, uint32_t b1) {
    asm volatile(
        "mma.sync.aligned.m16n8k8.row.col.f32.tf32.tf32.f32 "
        "{%0,%1,%2,%3}, {%4,%5,%6,%7}, {%8,%9}, {%0,%1,%2,%3};"
        : "+f"(c[0]), "+f"(c[1]), "+f"(c[2]), "+f"(c[3])
        : "r"(a0), "r"(a1), "r"(a2), "r"(a3), "r"(b0), "r"(b1));
}

// ======================= tf32 GEMM: C[rows,256] = A @ W + b =======================
// BM=128, BN=64, BK=32. 8 warps in 4x2 (m x n); warp tile 32x32.
__global__ __launch_bounds__(256) void gemm_tf32_kernel(
    const float* __restrict__ A, const float* __restrict__ W,
    const float* __restrict__ bias, float* __restrict__ C)
{
    __shared__ uint32_t As[128][36];   // [m][k], pad 36 -> conflict-free frags
    __shared__ uint32_t Ws[32][68];    // [k][n]

    const int tid    = threadIdx.x;
    const int lane   = tid & 31;
    const int wid    = tid >> 5;
    const int warp_m = wid & 3;        // 4 warps over 128 rows
    const int warp_n = wid >> 2;       // 2 warps over 64 cols
    const int row0   = blockIdx.y * 128;
    const int col0   = blockIdx.x * 64;

    float acc[2][4][4];
#pragma unroll
    for (int mt = 0; mt < 2; mt++)
#pragma unroll
        for (int nt = 0; nt < 4; nt++)
#pragma unroll
            for (int i = 0; i < 4; i++) acc[mt][nt][i] = 0.f;

    float4 ra[4], rw[2];
    // preload iter 0
#pragma unroll
    for (int u = 0; u < 4; u++) {
        int id = u * 256 + tid, r = id >> 3, kq = id & 7;
        ra[u] = *(const float4*)&A[(size_t)(row0 + r) * 256 + kq * 4];
    }
#pragma unroll
    for (int u = 0; u < 2; u++) {
        int id = u * 256 + tid, k = id >> 4, nq = id & 15;
        rw[u] = *(const float4*)&W[(size_t)k * 256 + col0 + nq * 4];
    }

    for (int it = 0; it < 8; it++) {
        // store current tile (tf32-converted)
#pragma unroll
        for (int u = 0; u < 4; u++) {
            int id = u * 256 + tid, r = id >> 3, kq = id & 7;
            As[r][kq * 4 + 0] = f2tf32(ra[u].x);
            As[r][kq * 4 + 1] = f2tf32(ra[u].y);
            As[r][kq * 4 + 2] = f2tf32(ra[u].z);
            As[r][kq * 4 + 3] = f2tf32(ra[u].w);
        }
#pragma unroll
        for (int u = 0; u < 2; u++) {
            int id = u * 256 + tid, k = id >> 4, nq = id & 15;
            Ws[k][nq * 4 + 0] = f2tf32(rw[u].x);
            Ws[k][nq * 4 + 1] = f2tf32(rw[u].y);
            Ws[k][nq * 4 + 2] = f2tf32(rw[u].z);
            Ws[k][nq * 4 + 3] = f2tf32(rw[u].w);
        }
        __syncthreads();

        // prefetch next
        if (it < 7) {
            const int k0n = (it + 1) * 32;
#pragma unroll
            for (int u = 0; u < 4; u++) {
                int id = u * 256 + tid, r = id >> 3, kq = id & 7;
                ra[u] = *(const float4*)&A[(size_t)(row0 + r) * 256 + k0n + kq * 4];
            }
#pragma unroll
            for (int u = 0; u < 2; u++) {
                int id = u * 256 + tid, k = id >> 4, nq = id & 15;
                rw[u] = *(const float4*)&W[(size_t)(k0n + k) * 256 + col0 + nq * 4];
            }
        }

        // compute: 4 ksteps of 8
#pragma unroll
        for (int kk = 0; kk < 4; kk++) {
            const int ko = kk * 8;
            uint32_t af[2][4];
#pragma unroll
            for (int mt = 0; mt < 2; mt++) {
                const int mb = warp_m * 32 + mt * 16 + (lane >> 2);
                const int kc = ko + (lane & 3);
                af[mt][0] = As[mb][kc];
                af[mt][1] = As[mb + 8][kc];
                af[mt][2] = As[mb][kc + 4];
                af[mt][3] = As[mb + 8][kc + 4];
            }
#pragma unroll
            for (int nt = 0; nt < 4; nt++) {
                const int nb = warp_n * 32 + nt * 8 + (lane >> 2);
                const int kr = ko + (lane & 3);
                uint32_t b0 = Ws[kr][nb];
                uint32_t b1 = Ws[kr + 4][nb];
#pragma unroll
                for (int mt = 0; mt < 2; mt++)
                    mma_tf32(acc[mt][nt], af[mt][0], af[mt][1], af[mt][2], af[mt][3], b0, b1);
            }
        }
        __syncthreads();
    }

    // epilogue
#pragma unroll
    for (int nt = 0; nt < 4; nt++) {
        const int col = col0 + warp_n * 32 + nt * 8 + (lane & 3) * 2;
        const float b0 = bias[col], b1 = bias[col + 1];
#pragma unroll
        for (int mt = 0; mt < 2; mt++) {
            const int row = row0 + warp_m * 32 + mt * 16 + (lane >> 2);
            float2 lo = make_float2(acc[mt][nt][0] + b0, acc[mt][nt][1] + b1);
            float2 hi = make_float2(acc[mt][nt][2] + b0, acc[mt][nt][3] + b1);
            *(float2*)&C[(size_t)row * 256 + col] = lo;
            *(float2*)&C[(size_t)(row + 8) * 256 + col] = hi;
        }
    }
}

// ======================= dual tf32 GEMM: K and V share the A tile =======================
__global__ __launch_bounds__(256) void gemm_tf32_dual_kernel(
    const float* __restrict__ A,
    const float* __restrict__ WK, const float* __restrict__ bK,
    const float* __restrict__ WV, const float* __restrict__ bV,
    float* __restrict__ CK, float* __restrict__ CV)
{
    __shared__ uint32_t As[128][36];
    __shared__ uint32_t WsK[32][68];
    __shared__ uint32_t WsV[32][68];

    const int tid    = threadIdx.x;
    const int lane   = tid & 31;
    const int wid    = tid >> 5;
    const int warp_m = wid & 3;
    const int warp_n = wid >> 2;
    const int row0   = blockIdx.y * 128;
    const int col0   = blockIdx.x * 64;

    float accK[2][4][4], accV[2][4][4];
#pragma unroll
    for (int mt = 0; mt < 2; mt++)
#pragma unroll
        for (int nt = 0; nt < 4; nt++)
#pragma unroll
            for (int i = 0; i < 4; i++) { accK[mt][nt][i] = 0.f; accV[mt][nt][i] = 0.f; }

    float4 ra[4], rk[2], rv[2];
#pragma unroll
    for (int u = 0; u < 4; u++) {
        int id = u * 256 + tid, r = id >> 3, kq = id & 7;
        ra[u] = *(const float4*)&A[(size_t)(row0 + r) * 256 + kq * 4];
    }
#pragma unroll
    for (int u = 0; u < 2; u++) {
        int id = u * 256 + tid, k = id >> 4, nq = id & 15;
        rk[u] = *(const float4*)&WK[(size_t)k * 256 + col0 + nq * 4];
        rv[u] = *(const float4*)&WV[(size_t)k * 256 + col0 + nq * 4];
    }

    for (int it = 0; it < 8; it++) {
#pragma unroll
        for (int u = 0; u < 4; u++) {
            int id = u * 256 + tid, r = id >> 3, kq = id & 7;
            As[r][kq * 4 + 0] = f2tf32(ra[u].x);
            As[r][kq * 4 + 1] = f2tf32(ra[u].y);
            As[r][kq * 4 + 2] = f2tf32(ra[u].z);
            As[r][kq * 4 + 3] = f2tf32(ra[u].w);
        }
#pragma unroll
        for (int u = 0; u < 2; u++) {
            int id = u * 256 + tid, k = id >> 4, nq = id & 15;
            WsK[k][nq * 4 + 0] = f2tf32(rk[u].x);
            WsK[k][nq * 4 + 1] = f2tf32(rk[u].y);
            WsK[k][nq * 4 + 2] = f2tf32(rk[u].z);
            WsK[k][nq * 4 + 3] = f2tf32(rk[u].w);
            WsV[k][nq * 4 + 0] = f2tf32(rv[u].x);
            WsV[k][nq * 4 + 1] = f2tf32(rv[u].y);
            WsV[k][nq * 4 + 2] = f2tf32(rv[u].z);
            WsV[k][nq * 4 + 3] = f2tf32(rv[u].w);
        }
        __syncthreads();

        if (it < 7) {
            const int k0n = (it + 1) * 32;
#pragma unroll
            for (int u = 0; u < 4; u++) {
                int id = u * 256 + tid, r = id >> 3, kq = id & 7;
                ra[u] = *(const float4*)&A[(size_t)(row0 + r) * 256 + k0n + kq * 4];
            }
#pragma unroll
            for (int u = 0; u < 2; u++) {
                int id = u * 256 + tid, k = id >> 4, nq = id & 15;
                rk[u] = *(const float4*)&WK[(size_t)(k0n + k) * 256 + col0 + nq * 4];
                rv[u] = *(const float4*)&WV[(size_t)(k0n + k) * 256 + col0 + nq * 4];
            }
        }

#pragma unroll
        for (int kk = 0; kk < 4; kk++) {
            const int ko = kk * 8;
            uint32_t af[2][4];
#pragma unroll
            for (int mt = 0; mt < 2; mt++) {
                const int mb = warp_m * 32 + mt * 16 + (lane >> 2);
                const int kc = ko + (lane & 3);
                af[mt][0] = As[mb][kc];
                af[mt][1] = As[mb + 8][kc];
                af[mt][2] = As[mb][kc + 4];
                af[mt][3] = As[mb + 8][kc + 4];
            }
#pragma unroll
            for (int nt = 0; nt < 4; nt++) {
                const int nb = warp_n * 32 + nt * 8 + (lane >> 2);
                const int kr = ko + (lane & 3);
                uint32_t bk0 = WsK[kr][nb], bk1 = WsK[kr + 4][nb];
                uint32_t bv0 = WsV[kr][nb], bv1 = WsV[kr + 4][nb];
#pragma unroll
                for (int mt = 0; mt < 2; mt++) {
                    mma_tf32(accK[mt][nt], af[mt][0], af[mt][1], af[mt][2], af[mt][3], bk0, bk1);
                    mma_tf32(accV[mt][nt], af[mt][0], af[mt][1], af[mt][2], af[mt][3], bv0, bv1);
                }
            }
        }
        __syncthreads();
    }

#pragma unroll
    for (int nt = 0; nt < 4; nt++) {
        const int col = col0 + warp_n * 32 + nt * 8 + (lane & 3) * 2;
        const float bk0 = bK[col], bk1 = bK[col + 1];
        const float bv0 = bV[col], bv1 = bV[col + 1];
#pragma unroll
        for (int mt = 0; mt < 2; mt++) {
            const int row = row0 + warp_m * 32 + mt * 16 + (lane >> 2);
            *(float2*)&CK[(size_t)row * 256 + col] =
                make_float2(accK[mt][nt][0] + bk0, accK[mt][nt][1] + bk1);
            *(float2*)&CK[(size_t)(row + 8) * 256 + col] =
                make_float2(accK[mt][nt][2] + bk0, accK[mt][nt][3] + bk1);
            *(float2*)&CV[(size_t)row * 256 + col] =
                make_float2(accV[mt][nt][0] + bv0, accV[mt][nt][1] + bv1);
            *(float2*)&CV[(size_t)(row + 8) * 256 + col] =
                make_float2(accV[mt][nt][2] + bv0, accV[mt][nt][3] + bv1);
        }
    }
}

// ======================= kNN: lazy-rescan top-16 =======================
__global__ __launch_bounds__(128) void knn_kernel(
    const float* __restrict__ src, const float* __restrict__ tgt,
    int* __restrict__ knn_idx)
{
    __shared__ float dist[Mk];
    __shared__ float lmin[128];
    __shared__ int   lidx[128];
    __shared__ int   s_win;

    const int qid = blockIdx.x;
    const int b   = qid / Nq;
    const int tid = threadIdx.x;

    const float qx = src[(size_t)qid * 3 + 0];
    const float qy = src[(size_t)qid * 3 + 1];
    const float qz = src[(size_t)qid * 3 + 2];
    const float qq = qx * qx + qy * qy + qz * qz;
    const float* tb = tgt + (size_t)b * Mk * 3;

    float bm = CUDART_INF_F;
    int   bi = Mk;
    for (int m = tid; m < Mk; m += 128) {
        float x = tb[(size_t)m * 3 + 0];
        float y = tb[(size_t)m * 3 + 1];
        float z = tb[(size_t)m * 3 + 2];
        float sq = fmaxf(qq + (x * x + y * y + z * z) - 2.f * (qx * x + qy * y + qz * z), 0.f);
        dist[m] = sq;
        if (sq < bm) { bm = sq; bi = m; }
    }
    lmin[tid] = bm; lidx[tid] = bi;
    __syncthreads();

    for (int it = 0; it < KNNk; it++) {
        if (tid < 32) {
            float v = lmin[tid]; int ix = lidx[tid];
#pragma unroll
            for (int j = 32; j < 128; j += 32) {
                float v2 = lmin[tid + j]; int i2 = lidx[tid + j];
                if (v2 < v || (v2 == v && i2 < ix)) { v = v2; ix = i2; }
            }
#pragma unroll
            for (int o = 16; o > 0; o >>= 1) {
                float v2 = __shfl_xor_sync(0xFFFFFFFFu, v, o);
                int   i2 = __shfl_xor_sync(0xFFFFFFFFu, ix, o);
                if (v2 < v || (v2 == v && i2 < ix)) { v = v2; ix = i2; }
            }
            if (tid == 0) {
                s_win = ix;
                knn_idx[(size_t)qid * KNNk + it] = ix;
                dist[ix] = CUDART_INF_F;
            }
        }
        __syncthreads();
        if (it < KNNk - 1) {
            int owner = s_win & 127;
            if (tid == owner) {
                float nb = CUDART_INF_F; int ni = Mk;
                for (int m = tid; m < Mk; m += 128) {
                    float v = dist[m];
                    if (v < nb) { nb = v; ni = m; }
                }
                lmin[tid] = nb; lidx[tid] = ni;
            }
            __syncthreads();
        }
    }
}

// ======================= sparse attention =======================
#define KSTRIDE 261

__global__ __launch_bounds__(256) void attn_kernel(const float* __restrict__ src_fea,
                                                   float* __restrict__ avg_attn)
{
    __shared__ int   sidx[KNNk];
    __shared__ float sq[Dd];
    __shared__ float sattn[Hh][KNNk];
    __shared__ float sK[KNNk][KSTRIDE];

    const int qid = blockIdx.x;
    const int b   = qid / Nq;
    const int tid = threadIdx.x;

    if (tid < KNNk) sidx[tid] = g_idx[(size_t)qid * KNNk + tid];
    sq[tid] = g_Q[(size_t)qid * Dd + tid];
    __syncthreads();

    // coalesced gather of 16 K rows
    {
        const int c4 = tid & 63;
        const int rg = tid >> 6;
#pragma unroll
        for (int it = 0; it < 4; it++) {
            const int r = rg + it * 4;
            float4 kv = *(const float4*)&g_K[((size_t)b * Mk + sidx[r]) * Dd + c4 * 4];
            sK[r][c4 * 4 + 0] = kv.x; sK[r][c4 * 4 + 1] = kv.y;
            sK[r][c4 * 4 + 2] = kv.z; sK[r][c4 * 4 + 3] = kv.w;
        }
    }
    __syncthreads();

    if (tid < Hh * KNNk) {
        const int h = tid >> 4;
        const int j = tid & 15;
        float s = 0.f;
#pragma unroll
        for (int d = 0; d < DK; d++) s += sq[h * DK + d] * sK[j][h * DK + d];
        s *= 0.17677669529663687f;

        float m = s;
#pragma unroll
        for (int o = 8; o > 0; o >>= 1) m = fmaxf(m, __shfl_xor_sync(0xFFFFFFFFu, m, o));
        float e = __expf(s - m);
        float sum = e;
#pragma unroll
        for (int o = 8; o > 0; o >>= 1) sum += __shfl_xor_sync(0xFFFFFFFFu, sum, o);
        sattn[h][j] = e / sum;
    }
    __syncthreads();

    // output: direct coalesced global V reads (L2-resident)
    {
        const int d = tid;
        const int h = d >> 5;
        const float* vb = &g_V[(size_t)b * Mk * Dd + d];
        float o = 0.f;
#pragma unroll
        for (int j = 0; j < KNNk; j++)
            o += sattn[h][j] * vb[(size_t)sidx[j] * Dd];
        g_X[(size_t)qid * Dd + d] = o + src_fea[(size_t)qid * Dd + d];
    }

    float* rowp = avg_attn + (size_t)qid * Mk;
    float4 z = make_float4(0.f, 0.f, 0.f, 0.f);
#pragma unroll
    for (int i = 0; i < 4; i++) ((float4*)rowp)[tid + i * 256] = z;
    __syncthreads();
    if (tid < KNNk) {
        float a = 0.f;
#pragma unroll
        for (int h = 0; h < Hh; h++) a += sattn[h][tid];
        rowp[sidx[tid]] = a * 0.125f;
    }
}

// ======================= LayerNorm + ReLU =======================
__global__ __launch_bounds__(256) void ln_relu_kernel(
    const float* __restrict__ T, const float* __restrict__ gam,
    const float* __restrict__ bet, float* __restrict__ Hb)
{
    __shared__ float red[8];
    const int row = blockIdx.x;
    const int tid = threadIdx.x;

    float x = T[(size_t)row * Dd + tid];

    float s = x;
#pragma unroll
    for (int o = 16; o > 0; o >>= 1) s += __shfl_xor_sync(0xFFFFFFFFu, s, o);
    if ((tid & 31) == 0) red[tid >> 5] = s;
    __syncthreads();
    float mu = (red[0] + red[1] + red[2] + red[3] + red[4] + red[5] + red[6] + red[7]) * (1.f / 256.f);
    __syncthreads();

    float dx = x - mu;
    float s2 = dx * dx;
#pragma unroll
    for (int o = 16; o > 0; o >>= 1) s2 += __shfl_xor_sync(0xFFFFFFFFu, s2, o);
    if ((tid & 31) == 0) red[tid >> 5] = s2;
    __syncthreads();
    float var = (red[0] + red[1] + red[2] + red[3] + red[4] + red[5] + red[6] + red[7]) * (1.f / 256.f);

    float y = dx * rsqrtf(var + 1e-5f) * gam[tid] + bet[tid];
    Hb[(size_t)row * Dd + tid] = fmaxf(y, 0.f);
}

// ======================= launch =======================
extern "C" void kernel_launch(void* const* d_in, const int* in_sizes, int n_in,
                              void* d_out, int out_size)
{
    const float* src     = (const float*)d_in[0];
    const float* tgt     = (const float*)d_in[1];
    const float* src_fea = (const float*)d_in[2];
    const float* tgt_fea = (const float*)d_in[3];
    const float* Wq  = (const float*)d_in[4];  const float* bq  = (const float*)d_in[5];
    const float* Wk  = (const float*)d_in[6];  const float* bk  = (const float*)d_in[7];
    const float* Wv  = (const float*)d_in[8];  const float* bv  = (const float*)d_in[9];
    const float* Wo1 = (const float*)d_in[10]; const float* bo1 = (const float*)d_in[11];
    const float* lng = (const float*)d_in[12]; const float* lnb = (const float*)d_in[13];
    const float* Wo2 = (const float*)d_in[14]; const float* bo2 = (const float*)d_in[15];

    float* outp = (float*)d_out;
    float* upd  = outp;
    float* avg  = outp + (size_t)Bb * Nq * Dd;

    float *pQ, *pK, *pV, *pX, *pT, *pHb; int* pIdx;
    cudaGetSymbolAddress((void**)&pQ,  g_Q);
    cudaGetSymbolAddress((void**)&pK,  g_K);
    cudaGetSymbolAddress((void**)&pV,  g_V);
    cudaGetSymbolAddress((void**)&pX,  g_X);
    cudaGetSymbolAddress((void**)&pT,  g_T);
    cudaGetSymbolAddress((void**)&pHb, g_Hb);
    cudaGetSymbolAddress((void**)&pIdx, g_idx);

    knn_kernel<<<Bb * Nq, 128>>>(src, tgt, pIdx);

    gemm_tf32_kernel<<<dim3(4, (Bb * Nq) / 128), 256>>>(src_fea, Wq, bq, pQ);
    gemm_tf32_dual_kernel<<<dim3(4, (Bb * Mk) / 128), 256>>>(tgt_fea, Wk, bk, Wv, bv, pK, pV);

    attn_kernel<<<Bb * Nq, 256>>>(src_fea, avg);

    gemm_tf32_kernel<<<dim3(4, (Bb * Nq) / 128), 256>>>(pX, Wo1, bo1, pT);
    ln_relu_kernel<<<Bb * Nq, 256>>>(pT, lng, lnb, pHb);
    gemm_tf32_kernel<<<dim3(4, (Bb * Nq) / 128), 256>>>(pHb, Wo2, bo2, upd);
}